// round 2
// baseline (speedup 1.0000x reference)
#include <cuda_runtime.h>
#include <cuda_bf16.h>

// Problem: cos_t [N=4096, C=100000] fp32, y_true [N,1] int64-or-int32.
// Output: (cos_t passthrough, mean of cos_t[i, y[i]]).

#define N_ROWS 4096
#define C_COLS 100000

__global__ void gather_mean_kernel(const float* __restrict__ cos_t,
                                   const int* __restrict__ y_words,
                                   float* __restrict__ out_scalar) {
    // One block, 1024 threads.
    __shared__ float sdata[1024];
    __shared__ int is_int64;

    int tid = threadIdx.x;

    // --- dtype detection: read only first 4096 int32 words (16 KB),
    // safe whether the buffer is int32 (16 KB) or int64 (32 KB). ---
    if (tid < 32) {
        // Check odd words 1,3,...,63: for int64 labels < 2^31 they are all 0.
        int w = y_words[2 * tid + 1];
        unsigned ballot = __ballot_sync(0xFFFFFFFFu, w != 0);
        if (tid == 0) is_int64 = (ballot == 0u) ? 1 : 0;
    }
    __syncthreads();
    const bool i64 = (is_int64 != 0);

    float acc = 0.0f;
    #pragma unroll
    for (int k = 0; k < 4; k++) {
        int row = tid + k * 1024;
        long long col;
        if (i64) {
            // little-endian int64: low word at index 2*row
            col = (long long)y_words[2 * row];
        } else {
            col = (long long)y_words[row];
        }
        // clamp defensively — never fault
        if (col < 0) col = 0;
        if (col >= C_COLS) col = C_COLS - 1;
        acc += cos_t[(long long)row * C_COLS + col];
    }
    sdata[tid] = acc;
    __syncthreads();
    for (int s = 512; s > 0; s >>= 1) {
        if (tid < s) sdata[tid] += sdata[tid + s];
        __syncthreads();
    }
    if (tid == 0) {
        *out_scalar = sdata[0] / (float)N_ROWS;
    }
}

extern "C" void kernel_launch(void* const* d_in, const int* in_sizes, int n_in,
                              void* d_out, int out_size) {
    // Identify inputs by element count, not position.
    const float* cos_t = nullptr;
    const int*   y_w   = nullptr;
    long long big = -1;
    int big_i = 0, small_i = 1;
    for (int i = 0; i < n_in; i++) {
        if ((long long)in_sizes[i] > big) { big = in_sizes[i]; big_i = i; }
    }
    for (int i = 0; i < n_in; i++) if (i != big_i) { small_i = i; break; }
    cos_t = (const float*)d_in[big_i];
    y_w   = (const int*)d_in[small_i];

    float* out = (float*)d_out;
    const long long total = (long long)N_ROWS * (long long)C_COLS;

    if ((long long)out_size >= total + 1) {
        // Layout: [cos_t (N*C floats)][scalar]
        gather_mean_kernel<<<1, 1024>>>(cos_t, y_w, out + total);
        cudaMemcpyAsync(out, cos_t, (size_t)total * sizeof(float),
                        cudaMemcpyDeviceToDevice, 0);
    } else if (out_size == 1) {
        // Scalar-only output
        gather_mean_kernel<<<1, 1024>>>(cos_t, y_w, out);
    } else {
        // Unknown layout: write scalar at the last slot, copy what fits.
        long long ncopy = (long long)out_size - 1;
        if (ncopy > total) ncopy = total;
        gather_mean_kernel<<<1, 1024>>>(cos_t, y_w, out + out_size - 1);
        if (ncopy > 0)
            cudaMemcpyAsync(out, cos_t, (size_t)ncopy * sizeof(float),
                            cudaMemcpyDeviceToDevice, 0);
    }
}

// round 3
// speedup vs baseline: 2.1784x; 2.1784x over previous
#include <cuda_runtime.h>
#include <cuda_bf16.h>

// cos_t [4096, 100000] fp32, y_true [4096,1] int64-or-int32.
// Output: [cos_t passthrough (N*C floats)][mean scalar].

#define N_ROWS 4096
#define C_COLS 100000

__global__ __launch_bounds__(1024)
void fused_copy_gather_kernel(const float4* __restrict__ src4,
                              float4* __restrict__ dst4,
                              const float* __restrict__ cos_t,
                              const int* __restrict__ y_words,
                              float* __restrict__ out_scalar,
                              long long n4) {
    int tid = threadIdx.x;

    // ---- Block 0: gather + mean (runs once, then joins the copy) ----
    if (blockIdx.x == 0) {
        __shared__ float sdata[1024];
        __shared__ int is_int64;
        if (tid < 32) {
            // int64 labels < 2^31 have zero hi-words at odd int32 indices.
            int w = y_words[2 * tid + 1];
            unsigned ballot = __ballot_sync(0xFFFFFFFFu, w != 0);
            if (tid == 0) is_int64 = (ballot == 0u) ? 1 : 0;
        }
        __syncthreads();
        const bool i64 = (is_int64 != 0);

        float acc = 0.0f;
        #pragma unroll
        for (int k = 0; k < 4; k++) {
            int row = tid + k * 1024;
            long long col = i64 ? (long long)y_words[2 * row]
                                : (long long)y_words[row];
            if (col < 0) col = 0;
            if (col >= C_COLS) col = C_COLS - 1;
            acc += cos_t[(long long)row * C_COLS + col];
        }
        sdata[tid] = acc;
        __syncthreads();
        for (int s = 512; s > 0; s >>= 1) {
            if (tid < s) sdata[tid] += sdata[tid + s];
            __syncthreads();
        }
        if (tid == 0) *out_scalar = sdata[0] / (float)N_ROWS;
    }

    // ---- All blocks: grid-stride float4 copy ----
    long long i = (long long)blockIdx.x * blockDim.x + tid;
    long long stride = (long long)gridDim.x * blockDim.x;
    for (; i < n4; i += stride) {
        dst4[i] = src4[i];
    }
}

extern "C" void kernel_launch(void* const* d_in, const int* in_sizes, int n_in,
                              void* d_out, int out_size) {
    // Identify inputs by element count.
    long long big = -1;
    int big_i = 0, small_i = 1;
    for (int i = 0; i < n_in; i++)
        if ((long long)in_sizes[i] > big) { big = in_sizes[i]; big_i = i; }
    for (int i = 0; i < n_in; i++) if (i != big_i) { small_i = i; break; }

    const float* cos_t = (const float*)d_in[big_i];
    const int*   y_w   = (const int*)d_in[small_i];
    float* out = (float*)d_out;

    const long long total = (long long)N_ROWS * (long long)C_COLS; // 409,600,000
    const long long n4 = total / 4;                                 // divisible

    // Expected layout: [cos_t][scalar]
    fused_copy_gather_kernel<<<2048, 1024>>>(
        (const float4*)cos_t, (float4*)out,
        cos_t, y_w, out + total, n4);
}

// round 4
// speedup vs baseline: 2.1895x; 1.0051x over previous
#include <cuda_runtime.h>
#include <cuda_bf16.h>

// cos_t [4096, 100000] fp32, y_true [4096,1] int64-or-int32.
// Output: [cos_t passthrough (N*C floats)][mean scalar].

#define N_ROWS 4096
#define C_COLS 100000

__global__ __launch_bounds__(1024)
void fused_copy_gather_kernel(const float4* __restrict__ src4,
                              float4* __restrict__ dst4,
                              const float* __restrict__ cos_t,
                              const int* __restrict__ y_words,
                              float* __restrict__ out_scalar,
                              long long n4) {
    int tid = threadIdx.x;

    // ---- Block 0: gather + mean (then joins the copy) ----
    if (blockIdx.x == 0) {
        __shared__ float sdata[1024];
        __shared__ int is_int64;
        if (tid < 32) {
            // int64 labels < 2^31 have zero hi-words at odd int32 indices.
            int w = y_words[2 * tid + 1];
            unsigned ballot = __ballot_sync(0xFFFFFFFFu, w != 0);
            if (tid == 0) is_int64 = (ballot == 0u) ? 1 : 0;
        }
        __syncthreads();
        const bool i64 = (is_int64 != 0);

        float acc = 0.0f;
        #pragma unroll
        for (int k = 0; k < 4; k++) {
            int row = tid + k * 1024;
            long long col = i64 ? (long long)y_words[2 * row]
                                : (long long)y_words[row];
            if (col < 0) col = 0;
            if (col >= C_COLS) col = C_COLS - 1;
            acc += cos_t[(long long)row * C_COLS + col];
        }
        sdata[tid] = acc;
        __syncthreads();
        for (int s = 512; s > 0; s >>= 1) {
            if (tid < s) sdata[tid] += sdata[tid + s];
            __syncthreads();
        }
        if (tid == 0) *out_scalar = sdata[0] / (float)N_ROWS;
    }

    // ---- All blocks: grid-stride streaming copy, 4x batched MLP ----
    const long long base   = (long long)blockIdx.x * blockDim.x + tid;
    const long long stride = (long long)gridDim.x * blockDim.x;

    long long i = base;
    // Main unrolled loop: 4 independent streaming loads, then 4 stores.
    for (; i + 3 * stride < n4; i += 4 * stride) {
        float4 a = __ldcs(&src4[i]);
        float4 b = __ldcs(&src4[i + stride]);
        float4 c = __ldcs(&src4[i + 2 * stride]);
        float4 d = __ldcs(&src4[i + 3 * stride]);
        __stcs(&dst4[i],              a);
        __stcs(&dst4[i + stride],     b);
        __stcs(&dst4[i + 2 * stride], c);
        __stcs(&dst4[i + 3 * stride], d);
    }
    // Tail
    for (; i < n4; i += stride) {
        __stcs(&dst4[i], __ldcs(&src4[i]));
    }
}

extern "C" void kernel_launch(void* const* d_in, const int* in_sizes, int n_in,
                              void* d_out, int out_size) {
    // Identify inputs by element count.
    long long big = -1;
    int big_i = 0, small_i = 1;
    for (int i = 0; i < n_in; i++)
        if ((long long)in_sizes[i] > big) { big = in_sizes[i]; big_i = i; }
    for (int i = 0; i < n_in; i++) if (i != big_i) { small_i = i; break; }

    const float* cos_t = (const float*)d_in[big_i];
    const int*   y_w   = (const int*)d_in[small_i];
    float* out = (float*)d_out;

    const long long total = (long long)N_ROWS * (long long)C_COLS; // 409,600,000
    const long long n4 = total / 4;                                 // divisible

    fused_copy_gather_kernel<<<2048, 1024>>>(
        (const float4*)cos_t, (float4*)out,
        cos_t, y_w, out + total, n4);
}